// round 1
// baseline (speedup 1.0000x reference)
#include <cuda_runtime.h>
#include <math.h>

#define B_ 1024
#define N_ 49
#define E_ 2048
#define D_ 512
#define A_ 512
#define M_ (B_ * N_)   // 50176

// out layout: [awe B*E][alpha B*N][beta B]
#define AWE_OFF   0
#define ALPHA_OFF (B_ * E_)                // 2097152
#define BETA_OFF  (ALPHA_OFF + B_ * N_)    // 2147328

// scratch (device globals: no allocation allowed)
__device__ float g_att2[B_ * A_];      // [B, A] = att2 + b_dec + b_enc
__device__ float g_attp[4 * M_];       // 4 a-chunk partials of att[m]

// ---------------------------------------------------------------------------
// Kernel 1: att2[b,a] = dot(dh[b], W_dec[a]) + b_dec[a] + b_enc[a]
// 8 b's per block to amortize W_dec traffic.
// ---------------------------------------------------------------------------
__global__ __launch_bounds__(256)
void k_att2(const float* __restrict__ dh, const float* __restrict__ Wdec,
            const float* __restrict__ b_enc, const float* __restrict__ b_dec)
{
    __shared__ float dhs[8][D_];
    const int b0 = blockIdx.x * 8;
    const int t = threadIdx.x;
    for (int i = t; i < 8 * D_; i += 256)
        dhs[i >> 9][i & 511] = dh[(size_t)b0 * D_ + i];
    __syncthreads();

    for (int a = t; a < A_; a += 256) {
        const float bias = b_dec[a] + b_enc[a];
        float acc[8];
        #pragma unroll
        for (int j = 0; j < 8; j++) acc[j] = 0.f;
        const float* w = Wdec + (size_t)a * D_;
        for (int k = 0; k < D_; k += 4) {
            const float4 wv = *(const float4*)(w + k);
            #pragma unroll
            for (int j = 0; j < 8; j++) {
                acc[j] = fmaf(wv.x, dhs[j][k + 0],
                         fmaf(wv.y, dhs[j][k + 1],
                         fmaf(wv.z, dhs[j][k + 2],
                         fmaf(wv.w, dhs[j][k + 3], acc[j]))));
            }
        }
        #pragma unroll
        for (int j = 0; j < 8; j++)
            g_att2[(size_t)(b0 + j) * A_ + a] = acc[j] + bias;
    }
}

// ---------------------------------------------------------------------------
// Kernel 2: fused main GEMM.
//  C[m,a] = sum_k enc[m,k] * W_enc[a,k]   (m = b*49+n, K = 2048)
//  epilogue: s[m] += sum_a relu(C[m,a] + att2[b,a]) * W_full[a]  (per a-chunk)
// Tiles: BM=128, BN=128, BK=16, 256 threads, 8x8 micro-tile.
// ---------------------------------------------------------------------------
#define BM 128
#define BN 128
#define BK 16
#define LDT 132   // padded smem row (132*4B = 528B, 16B aligned)

__global__ __launch_bounds__(256)
void k_main(const float* __restrict__ enc, const float* __restrict__ Wenc,
            const float* __restrict__ Wfull)
{
    __shared__ float As[BK][LDT];
    __shared__ float Bs[BK][LDT];
    __shared__ float Wfs[BN];

    const int aChunk = blockIdx.x;          // 0..3
    const int m0 = blockIdx.y * BM;         // 0..50048
    const int a0 = aChunk * BN;
    const int t  = threadIdx.x;
    const int tx = t & 15;
    const int ty = t >> 4;

    if (t < BN) Wfs[t] = Wfull[a0 + t];

    const float* Ap = enc  + (size_t)m0 * E_;
    const float* Bp = Wenc + (size_t)a0 * E_;

    // loader mapping: 2 rows per thread, 1 float4 each
    const int r0 = t >> 2;            // 0..63
    const int c0 = (t & 3) << 2;      // 0,4,8,12
    const int r1 = r0 + 64;

    // prologue: prefetch tile kt=0 into registers
    float4 av0 = *(const float4*)(Ap + (size_t)r0 * E_ + c0);
    float4 av1 = *(const float4*)(Ap + (size_t)r1 * E_ + c0);
    float4 bv0 = *(const float4*)(Bp + (size_t)r0 * E_ + c0);
    float4 bv1 = *(const float4*)(Bp + (size_t)r1 * E_ + c0);

    float acc[8][8];
    #pragma unroll
    for (int i = 0; i < 8; i++)
        #pragma unroll
        for (int j = 0; j < 8; j++) acc[i][j] = 0.f;

    for (int kt = 0; kt < E_; kt += BK) {
        __syncthreads();
        // store prefetched tile (transposed: As[k][m])
        As[c0 + 0][r0] = av0.x; As[c0 + 1][r0] = av0.y;
        As[c0 + 2][r0] = av0.z; As[c0 + 3][r0] = av0.w;
        As[c0 + 0][r1] = av1.x; As[c0 + 1][r1] = av1.y;
        As[c0 + 2][r1] = av1.z; As[c0 + 3][r1] = av1.w;
        Bs[c0 + 0][r0] = bv0.x; Bs[c0 + 1][r0] = bv0.y;
        Bs[c0 + 2][r0] = bv0.z; Bs[c0 + 3][r0] = bv0.w;
        Bs[c0 + 0][r1] = bv1.x; Bs[c0 + 1][r1] = bv1.y;
        Bs[c0 + 2][r1] = bv1.z; Bs[c0 + 3][r1] = bv1.w;
        __syncthreads();

        // prefetch next tile (overlaps with compute below)
        if (kt + BK < E_) {
            const int ko = kt + BK + c0;
            av0 = *(const float4*)(Ap + (size_t)r0 * E_ + ko);
            av1 = *(const float4*)(Ap + (size_t)r1 * E_ + ko);
            bv0 = *(const float4*)(Bp + (size_t)r0 * E_ + ko);
            bv1 = *(const float4*)(Bp + (size_t)r1 * E_ + ko);
        }

        #pragma unroll
        for (int kk = 0; kk < BK; kk++) {
            const float4 af0 = *(const float4*)&As[kk][ty << 2];
            const float4 af1 = *(const float4*)&As[kk][64 + (ty << 2)];
            const float4 bf0 = *(const float4*)&Bs[kk][tx << 2];
            const float4 bf1 = *(const float4*)&Bs[kk][64 + (tx << 2)];
            const float ar[8] = {af0.x, af0.y, af0.z, af0.w,
                                 af1.x, af1.y, af1.z, af1.w};
            const float br[8] = {bf0.x, bf0.y, bf0.z, bf0.w,
                                 bf1.x, bf1.y, bf1.z, bf1.w};
            #pragma unroll
            for (int i = 0; i < 8; i++)
                #pragma unroll
                for (int j = 0; j < 8; j++)
                    acc[i][j] = fmaf(ar[i], br[j], acc[i][j]);
        }
    }

    // epilogue: relu(acc + att2) . W_full, reduce over the 128 a-cols
    #pragma unroll
    for (int i = 0; i < 8; i++) {
        const int r = (i < 4) ? ((ty << 2) + i) : (64 + (ty << 2) + (i - 4));
        const int m = m0 + r;
        const int bidx = m / N_;
        const float* a2 = g_att2 + (size_t)bidx * A_ + a0;
        float s = 0.f;
        #pragma unroll
        for (int j = 0; j < 8; j++) {
            const int c = (j < 4) ? ((tx << 2) + j) : (64 + (tx << 2) + (j - 4));
            float v = acc[i][j] + a2[c];
            v = fmaxf(v, 0.f);
            s = fmaf(v, Wfs[c], s);
        }
        // reduce across the 16 lanes sharing this row (tx = 0..15, contiguous)
        s += __shfl_xor_sync(0xffffffffu, s, 1);
        s += __shfl_xor_sync(0xffffffffu, s, 2);
        s += __shfl_xor_sync(0xffffffffu, s, 4);
        s += __shfl_xor_sync(0xffffffffu, s, 8);
        if (tx == 0) g_attp[(size_t)aChunk * M_ + m] = s;
    }
}

// ---------------------------------------------------------------------------
// Kernel 3: per-b: beta = sigmoid(dh.W_sig + b_sig); softmax(att)*beta;
//           awe = sum_n alpha_n * enc[b,n,:]; write awe/alpha/beta.
// ---------------------------------------------------------------------------
__global__ __launch_bounds__(256)
void k_final(const float* __restrict__ enc, const float* __restrict__ dh,
             const float* __restrict__ Wsig, const float* __restrict__ bsig,
             const float* __restrict__ bfull, float* __restrict__ out)
{
    const int b = blockIdx.x;
    const int t = threadIdx.x;
    __shared__ float dhs[D_];
    __shared__ float red[256];
    __shared__ float alph[N_];
    __shared__ float beta_s;

    for (int i = t; i < D_; i += 256) dhs[i] = dh[(size_t)b * D_ + i];
    __syncthreads();

    // beta: block reduction of dh . W_sig
    red[t] = dhs[t] * Wsig[t] + dhs[t + 256] * Wsig[t + 256];
    __syncthreads();
    for (int s = 128; s > 0; s >>= 1) {
        if (t < s) red[t] += red[t + s];
        __syncthreads();
    }
    if (t == 0) beta_s = 1.f / (1.f + expf(-(red[0] + bsig[0])));

    // gather att partials
    if (t < N_) {
        float v = bfull[0];
        #pragma unroll
        for (int c = 0; c < 4; c++) v += g_attp[(size_t)c * M_ + b * N_ + t];
        alph[t] = v;
    }
    __syncthreads();

    if (t == 0) {
        float mx = -1e30f;
        for (int n = 0; n < N_; n++) mx = fmaxf(mx, alph[n]);
        float sm = 0.f;
        for (int n = 0; n < N_; n++) { float e = expf(alph[n] - mx); alph[n] = e; sm += e; }
        const float scale = beta_s / sm;
        for (int n = 0; n < N_; n++) alph[n] *= scale;
    }
    __syncthreads();

    if (t < N_) out[ALPHA_OFF + b * N_ + t] = alph[t];
    if (t == 0) out[BETA_OFF + b] = beta_s;

    // awe: 4-way ILP over e
    const float* eb = enc + (size_t)b * N_ * E_;
    for (int ebase = 0; ebase < E_; ebase += 1024) {
        float a0 = 0.f, a1 = 0.f, a2v = 0.f, a3 = 0.f;
        #pragma unroll 7
        for (int n = 0; n < N_; n++) {
            const float* p = eb + (size_t)n * E_ + ebase + t;
            const float al = alph[n];
            a0  = fmaf(al, p[0],   a0);
            a1  = fmaf(al, p[256], a1);
            a2v = fmaf(al, p[512], a2v);
            a3  = fmaf(al, p[768], a3);
        }
        float* o = out + AWE_OFF + (size_t)b * E_ + ebase + t;
        o[0]   = a0;
        o[256] = a1;
        o[512] = a2v;
        o[768] = a3;
    }
}

// ---------------------------------------------------------------------------
extern "C" void kernel_launch(void* const* d_in, const int* in_sizes, int n_in,
                              void* d_out, int out_size)
{
    (void)in_sizes; (void)n_in; (void)out_size;
    const float* enc  = (const float*)d_in[0];
    const float* dh   = (const float*)d_in[1];
    const float* Wenc = (const float*)d_in[2];
    const float* benc = (const float*)d_in[3];
    const float* Wdec = (const float*)d_in[4];
    const float* bdec = (const float*)d_in[5];
    const float* Wsig = (const float*)d_in[6];
    const float* bsig = (const float*)d_in[7];
    const float* Wful = (const float*)d_in[8];
    const float* bful = (const float*)d_in[9];
    float* out = (float*)d_out;

    k_att2<<<B_ / 8, 256>>>(dh, Wdec, benc, bdec);
    dim3 g2(A_ / BN, M_ / BM);
    k_main<<<g2, 256>>>(enc, Wenc, Wful);
    k_final<<<B_, 256>>>(enc, dh, Wsig, bsig, bful, out);
}

// round 3
// speedup vs baseline: 1.9388x; 1.9388x over previous
#include <cuda_runtime.h>
#include <cuda_bf16.h>
#include <math.h>
#include <stdint.h>

#define B_ 1024
#define N_ 49
#define E_ 2048
#define D_ 512
#define A_ 512
#define M_ (B_ * N_)   // 50176

// out layout: [awe B*E][alpha B*N][beta B]
#define AWE_OFF   0
#define ALPHA_OFF (B_ * E_)
#define BETA_OFF  (ALPHA_OFF + B_ * N_)

// scratch (device globals)
__device__ float g_att2[B_ * A_];                 // [B, A] = att2 + b_dec + b_enc
__device__ float g_attp[4 * M_];                  // 4 a-chunk partials of att[m]
__device__ __nv_bfloat16 g_Wh[A_ * E_];           // W_enc hi split
__device__ __nv_bfloat16 g_Wl[A_ * E_];           // W_enc lo split

// ---------------------------------------------------------------------------
__device__ __forceinline__ uint32_t smem_u32(const void* p) {
    return (uint32_t)__cvta_generic_to_shared((void*)p);
}
__device__ __forceinline__ void cpasync16(uint32_t dst, const void* src) {
    asm volatile("cp.async.cg.shared.global [%0], [%1], 16;" :: "r"(dst), "l"(src));
}
__device__ __forceinline__ void ldsm4(uint32_t* r, uint32_t addr) {
    asm volatile("ldmatrix.sync.aligned.m8n8.x4.shared.b16 {%0,%1,%2,%3}, [%4];"
                 : "=r"(r[0]), "=r"(r[1]), "=r"(r[2]), "=r"(r[3]) : "r"(addr));
}
__device__ __forceinline__ void mma16816(float* c, const uint32_t* a, const uint32_t* b) {
    asm volatile(
        "mma.sync.aligned.m16n8k16.row.col.f32.bf16.bf16.f32 "
        "{%0,%1,%2,%3}, {%4,%5,%6,%7}, {%8,%9}, {%0,%1,%2,%3};"
        : "+f"(c[0]), "+f"(c[1]), "+f"(c[2]), "+f"(c[3])
        : "r"(a[0]), "r"(a[1]), "r"(a[2]), "r"(a[3]), "r"(b[0]), "r"(b[1]));
}

// ---------------------------------------------------------------------------
// Kernel 0: split W_enc into bf16 hi/lo
// ---------------------------------------------------------------------------
__global__ __launch_bounds__(256)
void k_wconv(const float* __restrict__ W)
{
    const int i = (blockIdx.x * 256 + threadIdx.x) * 4;
    const float4 x = *(const float4*)(W + i);
    __nv_bfloat162 h0 = __floats2bfloat162_rn(x.x, x.y);
    __nv_bfloat162 h1 = __floats2bfloat162_rn(x.z, x.w);
    __nv_bfloat162 l0 = __floats2bfloat162_rn(x.x - __low2float(h0), x.y - __high2float(h0));
    __nv_bfloat162 l1 = __floats2bfloat162_rn(x.z - __low2float(h1), x.w - __high2float(h1));
    ((__nv_bfloat162*)g_Wh)[i / 2]     = h0;
    ((__nv_bfloat162*)g_Wh)[i / 2 + 1] = h1;
    ((__nv_bfloat162*)g_Wl)[i / 2]     = l0;
    ((__nv_bfloat162*)g_Wl)[i / 2 + 1] = l1;
}

// ---------------------------------------------------------------------------
// Kernel 1: att2[b,a] = dot(dh[b], W_dec[a]) + b_dec[a] + b_enc[a]
// ---------------------------------------------------------------------------
__global__ __launch_bounds__(256)
void k_att2(const float* __restrict__ dh, const float* __restrict__ Wdec,
            const float* __restrict__ b_enc, const float* __restrict__ b_dec)
{
    __shared__ float dhs[8][D_];
    const int b0 = blockIdx.x * 8;
    const int t = threadIdx.x;
    for (int i = t; i < 8 * D_; i += 256)
        dhs[i >> 9][i & 511] = dh[(size_t)b0 * D_ + i];
    __syncthreads();

    const int a = blockIdx.y * 256 + t;
    const float bias = b_dec[a] + b_enc[a];
    float acc[8];
    #pragma unroll
    for (int j = 0; j < 8; j++) acc[j] = 0.f;
    const float* w = Wdec + (size_t)a * D_;
    for (int k = 0; k < D_; k += 4) {
        const float4 wv = *(const float4*)(w + k);
        #pragma unroll
        for (int j = 0; j < 8; j++) {
            acc[j] = fmaf(wv.x, dhs[j][k + 0],
                     fmaf(wv.y, dhs[j][k + 1],
                     fmaf(wv.z, dhs[j][k + 2],
                     fmaf(wv.w, dhs[j][k + 3], acc[j]))));
        }
    }
    #pragma unroll
    for (int j = 0; j < 8; j++)
        g_att2[(size_t)(b0 + j) * A_ + a] = acc[j] + bias;
}

// ---------------------------------------------------------------------------
// Kernel 2: split-bf16 HMMA GEMM + fused epilogue.
//  C[m,a] = sum_k enc[m,k] * W_enc[a,k]; tile 128m x 128a, BK=32, 2 stages.
//  D += Ah*Bh + Ah*Bl + Al*Bh (fp32 accum).
//  Epilogue: g_attp[chunk*M + m] = sum_a relu(C + att2) * W_full.
// ---------------------------------------------------------------------------
#define BM 128
#define BK 32
#define NCHUNK (E_ / BK)     // 64
#define ROWB 80              // padded row bytes (32 bf16 = 64B -> 80B)

#define SM_ATT2   0          // 4*128*4 = 2048
#define SM_WF     2048       // 128*4 = 512
#define SM_RED    2560       // 128*4*4 = 2048
#define SM_STAGE0 5120
#define AH_OFF    0
#define AL_OFF    10240
#define BH_OFF    20480
#define BL_OFF    30720
#define STG       40960
#define SMEM_TOTAL (SM_STAGE0 + 2 * STG)   // 87040

__global__ __launch_bounds__(256, 1)
void k_main(const float* __restrict__ enc, const float* __restrict__ Wfull)
{
    extern __shared__ char smem[];
    const int t = threadIdx.x;
    const int lane = t & 31, wid = t >> 5;
    const int warp_m = wid & 1, warp_n = wid >> 1;
    const int chunkA = blockIdx.x;         // 0..3
    const int m0 = blockIdx.y * BM;
    const int a0 = chunkA * 128;
    const uint32_t sbase = smem_u32(smem);

    // epilogue constants
    const int b_first = m0 / N_;
    {
        float* att2s = (float*)(smem + SM_ATT2);
        for (int i = t; i < 4 * 128; i += 256) {
            const int br = b_first + (i >> 7);
            att2s[i] = (br < B_) ? g_att2[(size_t)br * A_ + a0 + (i & 127)] : 0.f;
        }
        if (t < 128) ((float*)(smem + SM_WF))[t] = Wfull[a0 + t];
    }

    // ---- loaders ----
    float4 areg[4];  // this thread's 16 floats of the next A chunk
    const float* ap = enc + (size_t)(m0 + (t >> 1)) * E_ + (t & 1) * 16;

    auto ldA = [&](int c) {
        const float4* p = (const float4*)(ap + c * BK);
        #pragma unroll
        for (int i = 0; i < 4; i++) areg[i] = p[i];
    };
    auto stsA = [&](int j) {
        char* bh = smem + SM_STAGE0 + j * STG + AH_OFF;
        char* bl = smem + SM_STAGE0 + j * STG + AL_OFF;
        const uint32_t off = (uint32_t)((t >> 1) * ROWB + (t & 1) * 32);
        uint32_t h[8], l[8];
        #pragma unroll
        for (int i = 0; i < 4; i++) {
            const float4 x = areg[i];
            __nv_bfloat162 hh0 = __floats2bfloat162_rn(x.x, x.y);
            __nv_bfloat162 hh1 = __floats2bfloat162_rn(x.z, x.w);
            __nv_bfloat162 ll0 = __floats2bfloat162_rn(x.x - __low2float(hh0), x.y - __high2float(hh0));
            __nv_bfloat162 ll1 = __floats2bfloat162_rn(x.z - __low2float(hh1), x.w - __high2float(hh1));
            h[2 * i] = *(uint32_t*)&hh0; h[2 * i + 1] = *(uint32_t*)&hh1;
            l[2 * i] = *(uint32_t*)&ll0; l[2 * i + 1] = *(uint32_t*)&ll1;
        }
        *(uint4*)(bh + off)      = make_uint4(h[0], h[1], h[2], h[3]);
        *(uint4*)(bh + off + 16) = make_uint4(h[4], h[5], h[6], h[7]);
        *(uint4*)(bl + off)      = make_uint4(l[0], l[1], l[2], l[3]);
        *(uint4*)(bl + off + 16) = make_uint4(l[4], l[5], l[6], l[7]);
    };
    auto cpB = [&](int c, int j) {
        const uint32_t bh = sbase + SM_STAGE0 + j * STG + BH_OFF;
        const uint32_t bl = sbase + SM_STAGE0 + j * STG + BL_OFF;
        #pragma unroll
        for (int i = 0; i < 2; i++) {
            const int idx = t + 256 * i;
            const int row = idx >> 2, u = idx & 3;
            const uint32_t d = (uint32_t)(row * ROWB + u * 16);
            const size_t gs = (size_t)(a0 + row) * E_ + c * BK + u * 8;
            cpasync16(bh + d, g_Wh + gs);
            cpasync16(bl + d, g_Wl + gs);
        }
        asm volatile("cp.async.commit_group;" ::: "memory");
    };

    float acc[4][4][4];
    #pragma unroll
    for (int i = 0; i < 4; i++)
        #pragma unroll
        for (int j = 0; j < 4; j++)
            #pragma unroll
            for (int q = 0; q < 4; q++) acc[i][j][q] = 0.f;

    // ---- prologue ----
    ldA(0);
    __syncthreads();           // att2s/wf fill done; also before first stsA
    stsA(0);
    cpB(0, 0);
    ldA(1);

    // ---- pipeline: one __syncthreads per iteration ----
    for (int c = 0; c < NCHUNK; c++) {
        const int j = c & 1, jn = j ^ 1;

        asm volatile("cp.async.wait_group 0;" ::: "memory");
        __syncthreads();   // B(stage j) visible; compute(c-1) done -> stage jn free

        if (c + 1 < NCHUNK) {
            stsA(jn);                      // areg holds chunk c+1
            cpB(c + 1, jn);
            if (c + 2 < NCHUNK) ldA(c + 2);
        }

        const uint32_t abase = sbase + SM_STAGE0 + j * STG;
        #pragma unroll
        for (int ks = 0; ks < 2; ks++) {
            uint32_t ah[4][4], al[4][4], bhf[4][2], blf[4][2];
            #pragma unroll
            for (int mt = 0; mt < 4; mt++) {
                const uint32_t addr = abase
                    + (uint32_t)((warp_m * 64 + mt * 16 + (lane & 15)) * ROWB)
                    + (uint32_t)((lane >> 4) * 16 + ks * 32);
                ldsm4(ah[mt], addr + AH_OFF);
                ldsm4(al[mt], addr + AL_OFF);
            }
            #pragma unroll
            for (int pt = 0; pt < 2; pt++) {
                const uint32_t row = (uint32_t)(warp_n * 32 + pt * 16
                                   + ((lane >> 4) << 3) + (lane & 7));
                const uint32_t addr = abase + (uint32_t)(row * ROWB)
                    + (uint32_t)(((lane >> 3) & 1) * 16 + ks * 32);
                uint32_t r[4];
                ldsm4(r, addr + BH_OFF);
                bhf[2 * pt][0] = r[0]; bhf[2 * pt][1] = r[1];
                bhf[2 * pt + 1][0] = r[2]; bhf[2 * pt + 1][1] = r[3];
                ldsm4(r, addr + BL_OFF);
                blf[2 * pt][0] = r[0]; blf[2 * pt][1] = r[1];
                blf[2 * pt + 1][0] = r[2]; blf[2 * pt + 1][1] = r[3];
            }
            #pragma unroll
            for (int mt = 0; mt < 4; mt++)
                #pragma unroll
                for (int nt = 0; nt < 4; nt++) {
                    mma16816(acc[mt][nt], ah[mt], bhf[nt]);
                    mma16816(acc[mt][nt], ah[mt], blf[nt]);
                    mma16816(acc[mt][nt], al[mt], bhf[nt]);
                }
        }
    }

    // ---- epilogue ----
    const float* att2s = (const float*)(smem + SM_ATT2);
    const float* wfs   = (const float*)(smem + SM_WF);
    float* red         = (float*)(smem + SM_RED);   // [128][4]

    #pragma unroll
    for (int mt = 0; mt < 4; mt++) {
        const int r0 = warp_m * 64 + mt * 16 + (lane >> 2);
        const int r1 = r0 + 8;
        const int bl0 = (m0 + r0) / N_ - b_first;
        const int bl1 = (m0 + r1) / N_ - b_first;
        float s0 = 0.f, s1 = 0.f;
        #pragma unroll
        for (int nt = 0; nt < 4; nt++) {
            const int cb = warp_n * 32 + nt * 8 + (lane & 3) * 2;
            float v;
            v = fmaxf(acc[mt][nt][0] + att2s[bl0 * 128 + cb],     0.f); s0 = fmaf(v, wfs[cb],     s0);
            v = fmaxf(acc[mt][nt][1] + att2s[bl0 * 128 + cb + 1], 0.f); s0 = fmaf(v, wfs[cb + 1], s0);
            v = fmaxf(acc[mt][nt][2] + att2s[bl1 * 128 + cb],     0.f); s1 = fmaf(v, wfs[cb],     s1);
            v = fmaxf(acc[mt][nt][3] + att2s[bl1 * 128 + cb + 1], 0.f); s1 = fmaf(v, wfs[cb + 1], s1);
        }
        s0 += __shfl_xor_sync(0xffffffffu, s0, 1);
        s0 += __shfl_xor_sync(0xffffffffu, s0, 2);
        s1 += __shfl_xor_sync(0xffffffffu, s1, 1);
        s1 += __shfl_xor_sync(0xffffffffu, s1, 2);
        if ((lane & 3) == 0) {
            red[r0 * 4 + warp_n] = s0;
            red[r1 * 4 + warp_n] = s1;
        }
    }
    __syncthreads();
    if (t < 128) {
        const float s = red[t * 4] + red[t * 4 + 1] + red[t * 4 + 2] + red[t * 4 + 3];
        g_attp[(size_t)chunkA * M_ + m0 + t] = s;
    }
}

// ---------------------------------------------------------------------------
// Kernel 3: beta, softmax*beta, awe, final writes.
// ---------------------------------------------------------------------------
__global__ __launch_bounds__(256)
void k_final(const float* __restrict__ enc, const float* __restrict__ dh,
             const float* __restrict__ Wsig, const float* __restrict__ bsig,
             const float* __restrict__ bfull, float* __restrict__ out)
{
    const int b = blockIdx.x;
    const int t = threadIdx.x;
    __shared__ float dhs[D_];
    __shared__ float red[256];
    __shared__ float alph[N_];
    __shared__ float beta_s;

    for (int i = t; i < D_; i += 256) dhs[i] = dh[(size_t)b * D_ + i];
    __syncthreads();

    red[t] = dhs[t] * Wsig[t] + dhs[t + 256] * Wsig[t + 256];
    __syncthreads();
    for (int s = 128; s > 0; s >>= 1) {
        if (t < s) red[t] += red[t + s];
        __syncthreads();
    }
    if (t == 0) beta_s = 1.f / (1.f + expf(-(red[0] + bsig[0])));

    if (t < N_) {
        float v = bfull[0];
        #pragma unroll
        for (int c = 0; c < 4; c++) v += g_attp[(size_t)c * M_ + b * N_ + t];
        alph[t] = v;
    }
    __syncthreads();

    if (t == 0) {
        float mx = -1e30f;
        for (int n = 0; n < N_; n++) mx = fmaxf(mx, alph[n]);
        float sm = 0.f;
        for (int n = 0; n < N_; n++) { float e = expf(alph[n] - mx); alph[n] = e; sm += e; }
        const float scale = beta_s / sm;
        for (int n = 0; n < N_; n++) alph[n] *= scale;
    }
    __syncthreads();

    if (t < N_) out[ALPHA_OFF + b * N_ + t] = alph[t];
    if (t == 0) out[BETA_OFF + b] = beta_s;

    const float* eb = enc + (size_t)b * N_ * E_;
    for (int ebase = 0; ebase < E_; ebase += 1024) {
        float a0 = 0.f, a1 = 0.f, a2v = 0.f, a3 = 0.f;
        #pragma unroll 7
        for (int n = 0; n < N_; n++) {
            const float* p = eb + (size_t)n * E_ + ebase + t;
            const float al = alph[n];
            a0  = fmaf(al, p[0],   a0);
            a1  = fmaf(al, p[256], a1);
            a2v = fmaf(al, p[512], a2v);
            a3  = fmaf(al, p[768], a3);
        }
        float* o = out + AWE_OFF + (size_t)b * E_ + ebase + t;
        o[0]   = a0;
        o[256] = a1;
        o[512] = a2v;
        o[768] = a3;
    }
}

// ---------------------------------------------------------------------------
extern "C" void kernel_launch(void* const* d_in, const int* in_sizes, int n_in,
                              void* d_out, int out_size)
{
    (void)in_sizes; (void)n_in; (void)out_size;
    const float* enc  = (const float*)d_in[0];
    const float* dh   = (const float*)d_in[1];
    const float* Wenc = (const float*)d_in[2];
    const float* benc = (const float*)d_in[3];
    const float* Wdec = (const float*)d_in[4];
    const float* bdec = (const float*)d_in[5];
    const float* Wsig = (const float*)d_in[6];
    const float* bsig = (const float*)d_in[7];
    const float* Wful = (const float*)d_in[8];
    const float* bful = (const float*)d_in[9];
    float* out = (float*)d_out;

    cudaFuncSetAttribute(k_main, cudaFuncAttributeMaxDynamicSharedMemorySize, SMEM_TOTAL);

    k_wconv<<<(A_ * E_) / 1024, 256>>>(Wenc);
    k_att2<<<dim3(B_ / 8, 2), 256>>>(dh, Wdec, benc, bdec);
    k_main<<<dim3(4, M_ / BM), 256, SMEM_TOTAL>>>(enc, Wful);
    k_final<<<B_, 256>>>(enc, dh, Wsig, bsig, bful, out);
}

// round 4
// speedup vs baseline: 2.0380x; 1.0512x over previous
#include <cuda_runtime.h>
#include <cuda_bf16.h>
#include <math.h>
#include <stdint.h>

#define B_ 1024
#define N_ 49
#define E_ 2048
#define D_ 512
#define A_ 512
#define M_ (B_ * N_)   // 50176

// out layout: [awe B*E][alpha B*N][beta B]
#define AWE_OFF   0
#define ALPHA_OFF (B_ * E_)
#define BETA_OFF  (ALPHA_OFF + B_ * N_)

// scratch (device globals)
__device__ float g_att2[B_ * A_];                 // [B, A] = att2 + b_dec + b_enc
__device__ float g_attp[2 * M_];                  // 2 a-chunk partials of att[m]
__device__ __nv_bfloat16 g_Wh[A_ * E_];           // W_enc hi split
__device__ __nv_bfloat16 g_Wl[A_ * E_];           // W_enc lo split

// ---------------------------------------------------------------------------
__device__ __forceinline__ uint32_t smem_u32(const void* p) {
    return (uint32_t)__cvta_generic_to_shared((void*)p);
}
__device__ __forceinline__ void cpasync16(uint32_t dst, const void* src) {
    asm volatile("cp.async.cg.shared.global [%0], [%1], 16;" :: "r"(dst), "l"(src));
}
__device__ __forceinline__ void ldsm4(uint32_t* r, uint32_t addr) {
    asm volatile("ldmatrix.sync.aligned.m8n8.x4.shared.b16 {%0,%1,%2,%3}, [%4];"
                 : "=r"(r[0]), "=r"(r[1]), "=r"(r[2]), "=r"(r[3]) : "r"(addr));
}
__device__ __forceinline__ void mma16816(float* c, const uint32_t* a, const uint32_t* b) {
    asm volatile(
        "mma.sync.aligned.m16n8k16.row.col.f32.bf16.bf16.f32 "
        "{%0,%1,%2,%3}, {%4,%5,%6,%7}, {%8,%9}, {%0,%1,%2,%3};"
        : "+f"(c[0]), "+f"(c[1]), "+f"(c[2]), "+f"(c[3])
        : "r"(a[0]), "r"(a[1]), "r"(a[2]), "r"(a[3]), "r"(b[0]), "r"(b[1]));
}

// ---------------------------------------------------------------------------
// Kernel 0: split W_enc into bf16 hi/lo
// ---------------------------------------------------------------------------
__global__ __launch_bounds__(256)
void k_wconv(const float* __restrict__ W)
{
    const int i = (blockIdx.x * 256 + threadIdx.x) * 4;
    const float4 x = *(const float4*)(W + i);
    __nv_bfloat162 h0 = __floats2bfloat162_rn(x.x, x.y);
    __nv_bfloat162 h1 = __floats2bfloat162_rn(x.z, x.w);
    __nv_bfloat162 l0 = __floats2bfloat162_rn(x.x - __low2float(h0), x.y - __high2float(h0));
    __nv_bfloat162 l1 = __floats2bfloat162_rn(x.z - __low2float(h1), x.w - __high2float(h1));
    ((__nv_bfloat162*)g_Wh)[i / 2]     = h0;
    ((__nv_bfloat162*)g_Wh)[i / 2 + 1] = h1;
    ((__nv_bfloat162*)g_Wl)[i / 2]     = l0;
    ((__nv_bfloat162*)g_Wl)[i / 2 + 1] = l1;
}

// ---------------------------------------------------------------------------
// Kernel 1: att2[b,a] = dot(dh[b], W_dec[a]) + b_dec[a] + b_enc[a]
// 16 b's per block to amortize W_dec traffic; grid (B/16, 2).
// ---------------------------------------------------------------------------
__global__ __launch_bounds__(256)
void k_att2(const float* __restrict__ dh, const float* __restrict__ Wdec,
            const float* __restrict__ b_enc, const float* __restrict__ b_dec)
{
    __shared__ float dhs[16][D_];
    const int b0 = blockIdx.x * 16;
    const int t = threadIdx.x;
    for (int i = t; i < 16 * D_; i += 256)
        dhs[i >> 9][i & 511] = dh[(size_t)b0 * D_ + i];
    __syncthreads();

    const int a = blockIdx.y * 256 + t;
    const float bias = b_dec[a] + b_enc[a];
    float acc[16];
    #pragma unroll
    for (int j = 0; j < 16; j++) acc[j] = 0.f;
    const float* w = Wdec + (size_t)a * D_;
    for (int k = 0; k < D_; k += 4) {
        const float4 wv = *(const float4*)(w + k);
        #pragma unroll
        for (int j = 0; j < 16; j++) {
            acc[j] = fmaf(wv.x, dhs[j][k + 0],
                     fmaf(wv.y, dhs[j][k + 1],
                     fmaf(wv.z, dhs[j][k + 2],
                     fmaf(wv.w, dhs[j][k + 3], acc[j]))));
        }
    }
    #pragma unroll
    for (int j = 0; j < 16; j++)
        g_att2[(size_t)(b0 + j) * A_ + a] = acc[j] + bias;
}

// ---------------------------------------------------------------------------
// Kernel 2: split-bf16 HMMA GEMM + fused epilogue.
//  CTA tile 128m x 256a, BK=32, 3 stages, warp tile 64x64 (2x4 warps).
//  D += Ah*Bh + Ah*Bl + Al*Bh (fp32 accum).
//  Epilogue: g_attp[chunk*M + m] = sum_a relu(C + att2) * W_full.
// ---------------------------------------------------------------------------
#define BM 128
#define BN 256
#define BK 32
#define NCHUNK (E_ / BK)     // 64
#define ROWB 80              // padded row bytes (32 bf16 = 64B -> 80B)

#define SM_ATT2   0          // 4*256*4 = 4096
#define SM_WF     4096       // 256*4  = 1024
#define SM_RED    5120       // 128*4*4 = 2048
#define SM_STAGE0 8192
#define AH_OFF    0          // 128*80 = 10240
#define AL_OFF    10240
#define BH_OFF    20480      // 256*80 = 20480
#define BL_OFF    40960
#define STG       61440
#define SMEM_TOTAL (SM_STAGE0 + 3 * STG)   // 192512

__global__ __launch_bounds__(256, 1)
void k_main(const float* __restrict__ enc, const float* __restrict__ Wfull)
{
    extern __shared__ char smem[];
    const int t = threadIdx.x;
    const int lane = t & 31, wid = t >> 5;
    const int warp_m = wid & 1, warp_n = wid >> 1;   // 2 x 4
    const int chunkA = blockIdx.x;         // 0..1
    const int m0 = blockIdx.y * BM;
    const int a0 = chunkA * BN;
    const uint32_t sbase = smem_u32(smem);

    // epilogue constants
    const int b_first = m0 / N_;
    {
        float* att2s = (float*)(smem + SM_ATT2);
        for (int i = t; i < 4 * BN; i += 256) {
            const int br = b_first + (i >> 8);
            att2s[i] = (br < B_) ? g_att2[(size_t)br * A_ + a0 + (i & 255)] : 0.f;
        }
        ((float*)(smem + SM_WF))[t] = Wfull[a0 + t];
    }

    // ---- loaders ----
    float4 areg[4];  // this thread's 16 floats of a future A chunk
    const float* ap = enc + (size_t)(m0 + (t >> 1)) * E_ + (t & 1) * 16;

    auto ldA = [&](int c) {
        const float4* p = (const float4*)(ap + c * BK);
        #pragma unroll
        for (int i = 0; i < 4; i++) areg[i] = p[i];
    };
    auto stsA = [&](int st) {
        char* bh = smem + SM_STAGE0 + st * STG + AH_OFF;
        char* bl = smem + SM_STAGE0 + st * STG + AL_OFF;
        const uint32_t off = (uint32_t)((t >> 1) * ROWB + (t & 1) * 32);
        uint32_t h[8], l[8];
        #pragma unroll
        for (int i = 0; i < 4; i++) {
            const float4 x = areg[i];
            __nv_bfloat162 hh0 = __floats2bfloat162_rn(x.x, x.y);
            __nv_bfloat162 hh1 = __floats2bfloat162_rn(x.z, x.w);
            __nv_bfloat162 ll0 = __floats2bfloat162_rn(x.x - __low2float(hh0), x.y - __high2float(hh0));
            __nv_bfloat162 ll1 = __floats2bfloat162_rn(x.z - __low2float(hh1), x.w - __high2float(hh1));
            h[2 * i] = *(uint32_t*)&hh0; h[2 * i + 1] = *(uint32_t*)&hh1;
            l[2 * i] = *(uint32_t*)&ll0; l[2 * i + 1] = *(uint32_t*)&ll1;
        }
        *(uint4*)(bh + off)      = make_uint4(h[0], h[1], h[2], h[3]);
        *(uint4*)(bh + off + 16) = make_uint4(h[4], h[5], h[6], h[7]);
        *(uint4*)(bl + off)      = make_uint4(l[0], l[1], l[2], l[3]);
        *(uint4*)(bl + off + 16) = make_uint4(l[4], l[5], l[6], l[7]);
    };
    auto cpB = [&](int c, int st) {
        const uint32_t bh = sbase + SM_STAGE0 + st * STG + BH_OFF;
        const uint32_t bl = sbase + SM_STAGE0 + st * STG + BL_OFF;
        #pragma unroll
        for (int i = 0; i < 4; i++) {
            const int idx = t + 256 * i;
            const int row = idx >> 2, u = idx & 3;
            const uint32_t d = (uint32_t)(row * ROWB + u * 16);
            const size_t gs = (size_t)(a0 + row) * E_ + c * BK + u * 8;
            cpasync16(bh + d, g_Wh + gs);
            cpasync16(bl + d, g_Wl + gs);
        }
        asm volatile("cp.async.commit_group;" ::: "memory");
    };

    float acc[4][8][4];
    #pragma unroll
    for (int i = 0; i < 4; i++)
        #pragma unroll
        for (int j = 0; j < 8; j++)
            #pragma unroll
            for (int q = 0; q < 4; q++) acc[i][j][q] = 0.f;

    // ---- prologue: fill stages 0 and 1 ----
    ldA(0);
    stsA(0); cpB(0, 0);
    ldA(1);
    stsA(1); cpB(1, 1);
    ldA(2);

    int st_c = 0;   // stage holding chunk c
    // ---- pipeline ----
    for (int c = 0; c < NCHUNK; c++) {
        asm volatile("cp.async.wait_group 1;" ::: "memory");
        __syncthreads();   // B(chunk c) visible; stage (c+2)%3 free (compute c-1 done)

        if (c + 2 < NCHUNK) {
            const int st_f = (st_c + 2 >= 3) ? st_c + 2 - 3 : st_c + 2;
            stsA(st_f);                     // areg holds chunk c+2
            cpB(c + 2, st_f);
            if (c + 3 < NCHUNK) ldA(c + 3);
        } else {
            asm volatile("cp.async.commit_group;" ::: "memory");  // keep group count in sync
        }

        const uint32_t abase = sbase + SM_STAGE0 + st_c * STG;
        #pragma unroll
        for (int ks = 0; ks < 2; ks++) {
            uint32_t ah[4][4], al[4][4];
            #pragma unroll
            for (int mt = 0; mt < 4; mt++) {
                const uint32_t addr = abase
                    + (uint32_t)((warp_m * 64 + mt * 16 + (lane & 15)) * ROWB)
                    + (uint32_t)((lane >> 4) * 16 + ks * 32);
                ldsm4(ah[mt], addr + AH_OFF);
                ldsm4(al[mt], addr + AL_OFF);
            }
            #pragma unroll
            for (int pt = 0; pt < 4; pt++) {
                const uint32_t row = (uint32_t)(warp_n * 64 + pt * 16
                                   + ((lane >> 4) << 3) + (lane & 7));
                const uint32_t addr = abase + (uint32_t)(row * ROWB)
                    + (uint32_t)(((lane >> 3) & 1) * 16 + ks * 32);
                uint32_t bh[4], bl[4];
                ldsm4(bh, addr + BH_OFF);
                ldsm4(bl, addr + BL_OFF);
                #pragma unroll
                for (int mt = 0; mt < 4; mt++) {
                    mma16816(acc[mt][2 * pt],     ah[mt], bh);
                    mma16816(acc[mt][2 * pt],     ah[mt], bl);
                    mma16816(acc[mt][2 * pt],     al[mt], bh);
                    mma16816(acc[mt][2 * pt + 1], ah[mt], bh + 2);
                    mma16816(acc[mt][2 * pt + 1], ah[mt], bl + 2);
                    mma16816(acc[mt][2 * pt + 1], al[mt], bh + 2);
                }
            }
        }
        st_c = (st_c + 1 >= 3) ? 0 : st_c + 1;
    }

    // ---- epilogue ----
    const float* att2s = (const float*)(smem + SM_ATT2);
    const float* wfs   = (const float*)(smem + SM_WF);
    float* red         = (float*)(smem + SM_RED);   // [128][4]

    #pragma unroll
    for (int mt = 0; mt < 4; mt++) {
        const int r0 = warp_m * 64 + mt * 16 + (lane >> 2);
        const int r1 = r0 + 8;
        const int bl0 = (m0 + r0) / N_ - b_first;
        const int bl1 = (m0 + r1) / N_ - b_first;
        float s0 = 0.f, s1 = 0.f;
        #pragma unroll
        for (int nt = 0; nt < 8; nt++) {
            const int cb = warp_n * 64 + nt * 8 + (lane & 3) * 2;
            float v;
            v = fmaxf(acc[mt][nt][0] + att2s[bl0 * BN + cb],     0.f); s0 = fmaf(v, wfs[cb],     s0);
            v = fmaxf(acc[mt][nt][1] + att2s[bl0 * BN + cb + 1], 0.f); s0 = fmaf(v, wfs[cb + 1], s0);
            v = fmaxf(acc[mt][nt][2] + att2s[bl1 * BN + cb],     0.f); s1 = fmaf(v, wfs[cb],     s1);
            v = fmaxf(acc[mt][nt][3] + att2s[bl1 * BN + cb + 1], 0.f); s1 = fmaf(v, wfs[cb + 1], s1);
        }
        s0 += __shfl_xor_sync(0xffffffffu, s0, 1);
        s0 += __shfl_xor_sync(0xffffffffu, s0, 2);
        s1 += __shfl_xor_sync(0xffffffffu, s1, 1);
        s1 += __shfl_xor_sync(0xffffffffu, s1, 2);
        if ((lane & 3) == 0) {
            red[r0 * 4 + warp_n] = s0;
            red[r1 * 4 + warp_n] = s1;
        }
    }
    __syncthreads();
    if (t < 128) {
        const float s = red[t * 4] + red[t * 4 + 1] + red[t * 4 + 2] + red[t * 4 + 3];
        g_attp[(size_t)chunkA * M_ + m0 + t] = s;
    }
}

// ---------------------------------------------------------------------------
// Kernel 3: beta, softmax*beta, awe, final writes.
// ---------------------------------------------------------------------------
__global__ __launch_bounds__(256)
void k_final(const float* __restrict__ enc, const float* __restrict__ dh,
             const float* __restrict__ Wsig, const float* __restrict__ bsig,
             const float* __restrict__ bfull, float* __restrict__ out)
{
    const int b = blockIdx.x;
    const int t = threadIdx.x;
    __shared__ float dhs[D_];
    __shared__ float red[256];
    __shared__ float alph[N_];
    __shared__ float beta_s;

    for (int i = t; i < D_; i += 256) dhs[i] = dh[(size_t)b * D_ + i];
    __syncthreads();

    red[t] = dhs[t] * Wsig[t] + dhs[t + 256] * Wsig[t + 256];
    __syncthreads();
    for (int s = 128; s > 0; s >>= 1) {
        if (t < s) red[t] += red[t + s];
        __syncthreads();
    }
    if (t == 0) beta_s = 1.f / (1.f + expf(-(red[0] + bsig[0])));

    if (t < N_) {
        alph[t] = bfull[0] + g_attp[b * N_ + t] + g_attp[M_ + b * N_ + t];
    }
    __syncthreads();

    if (t == 0) {
        float mx = -1e30f;
        for (int n = 0; n < N_; n++) mx = fmaxf(mx, alph[n]);
        float sm = 0.f;
        for (int n = 0; n < N_; n++) { float e = expf(alph[n] - mx); alph[n] = e; sm += e; }
        const float scale = beta_s / sm;
        for (int n = 0; n < N_; n++) alph[n] *= scale;
    }
    __syncthreads();

    if (t < N_) out[ALPHA_OFF + b * N_ + t] = alph[t];
    if (t == 0) out[BETA_OFF + b] = beta_s;

    const float* eb = enc + (size_t)b * N_ * E_;
    for (int ebase = 0; ebase < E_; ebase += 1024) {
        float a0 = 0.f, a1 = 0.f, a2v = 0.f, a3 = 0.f;
        #pragma unroll 7
        for (int n = 0; n < N_; n++) {
            const float* p = eb + (size_t)n * E_ + ebase + t;
            const float al = alph[n];
            a0  = fmaf(al, p[0],   a0);
            a1  = fmaf(al, p[256], a1);
            a2v = fmaf(al, p[512], a2v);
            a3  = fmaf(al, p[768], a3);
        }
        float* o = out + AWE_OFF + (size_t)b * E_ + ebase + t;
        o[0]   = a0;
        o[256] = a1;
        o[512] = a2v;
        o[768] = a3;
    }
}

// ---------------------------------------------------------------------------
extern "C" void kernel_launch(void* const* d_in, const int* in_sizes, int n_in,
                              void* d_out, int out_size)
{
    (void)in_sizes; (void)n_in; (void)out_size;
    const float* enc  = (const float*)d_in[0];
    const float* dh   = (const float*)d_in[1];
    const float* Wenc = (const float*)d_in[2];
    const float* benc = (const float*)d_in[3];
    const float* Wdec = (const float*)d_in[4];
    const float* bdec = (const float*)d_in[5];
    const float* Wsig = (const float*)d_in[6];
    const float* bsig = (const float*)d_in[7];
    const float* Wful = (const float*)d_in[8];
    const float* bful = (const float*)d_in[9];
    float* out = (float*)d_out;

    cudaFuncSetAttribute(k_main, cudaFuncAttributeMaxDynamicSharedMemorySize, SMEM_TOTAL);

    k_wconv<<<(A_ * E_) / 1024, 256>>>(Wenc);
    k_att2<<<dim3(B_ / 16, 2), 256>>>(dh, Wdec, benc, bdec);
    k_main<<<dim3(2, M_ / BM), 256, SMEM_TOTAL>>>(enc, Wful);
    k_final<<<B_, 256>>>(enc, dh, Wsig, bsig, bful, out);
}

// round 6
// speedup vs baseline: 2.1604x; 1.0601x over previous
#include <cuda_runtime.h>
#include <cuda_bf16.h>
#include <math.h>
#include <stdint.h>

#define B_ 1024
#define N_ 49
#define E_ 2048
#define D_ 512
#define A_ 512
#define M_ (B_ * N_)   // 50176

// out layout: [awe B*E][alpha B*N][beta B]
#define AWE_OFF   0
#define ALPHA_OFF (B_ * E_)
#define BETA_OFF  (ALPHA_OFF + B_ * N_)

// scratch (device globals)
__device__ float g_att2[B_ * A_];                 // [B, A] = att2 + b_dec + b_enc
__device__ float g_attp[4 * M_];                  // 4 a-chunk partials of att[m]
__device__ __nv_bfloat16 g_Wh[A_ * E_];           // W_enc hi split
__device__ __nv_bfloat16 g_Wl[A_ * E_];           // W_enc lo split

// ---------------------------------------------------------------------------
__device__ __forceinline__ uint32_t smem_u32(const void* p) {
    return (uint32_t)__cvta_generic_to_shared((void*)p);
}
__device__ __forceinline__ void cpasync16(uint32_t dst, const void* src) {
    asm volatile("cp.async.cg.shared.global [%0], [%1], 16;" :: "r"(dst), "l"(src));
}
__device__ __forceinline__ void ldsm4(uint32_t* r, uint32_t addr) {
    asm volatile("ldmatrix.sync.aligned.m8n8.x4.shared.b16 {%0,%1,%2,%3}, [%4];"
                 : "=r"(r[0]), "=r"(r[1]), "=r"(r[2]), "=r"(r[3]) : "r"(addr));
}
// NOTE: non-volatile — register-only op, lets ptxas schedule/interleave.
__device__ __forceinline__ void mma16816(float* c, const uint32_t* a, const uint32_t* b) {
    asm("mma.sync.aligned.m16n8k16.row.col.f32.bf16.bf16.f32 "
        "{%0,%1,%2,%3}, {%4,%5,%6,%7}, {%8,%9}, {%0,%1,%2,%3};"
        : "+f"(c[0]), "+f"(c[1]), "+f"(c[2]), "+f"(c[3])
        : "r"(a[0]), "r"(a[1]), "r"(a[2]), "r"(a[3]), "r"(b[0]), "r"(b[1]));
}

// ---------------------------------------------------------------------------
// Kernel 0: split W_enc into bf16 hi/lo
// ---------------------------------------------------------------------------
__global__ __launch_bounds__(256)
void k_wconv(const float* __restrict__ W)
{
    const int i = (blockIdx.x * 256 + threadIdx.x) * 4;
    const float4 x = *(const float4*)(W + i);
    __nv_bfloat162 h0 = __floats2bfloat162_rn(x.x, x.y);
    __nv_bfloat162 h1 = __floats2bfloat162_rn(x.z, x.w);
    __nv_bfloat162 l0 = __floats2bfloat162_rn(x.x - __low2float(h0), x.y - __high2float(h0));
    __nv_bfloat162 l1 = __floats2bfloat162_rn(x.z - __low2float(h1), x.w - __high2float(h1));
    ((__nv_bfloat162*)g_Wh)[i / 2]     = h0;
    ((__nv_bfloat162*)g_Wh)[i / 2 + 1] = h1;
    ((__nv_bfloat162*)g_Wl)[i / 2]     = l0;
    ((__nv_bfloat162*)g_Wl)[i / 2 + 1] = l1;
}

// ---------------------------------------------------------------------------
// Kernel 1: att2[b,a] = dot(dh[b], W_dec[a]) + b_dec[a] + b_enc[a]
// ---------------------------------------------------------------------------
__global__ __launch_bounds__(256)
void k_att2(const float* __restrict__ dh, const float* __restrict__ Wdec,
            const float* __restrict__ b_enc, const float* __restrict__ b_dec)
{
    __shared__ float dhs[16][D_];
    const int b0 = blockIdx.x * 16;
    const int t = threadIdx.x;
    for (int i = t; i < 16 * D_; i += 256)
        dhs[i >> 9][i & 511] = dh[(size_t)b0 * D_ + i];
    __syncthreads();

    const int a = blockIdx.y * 256 + t;
    const float bias = b_dec[a] + b_enc[a];
    float acc[16];
    #pragma unroll
    for (int j = 0; j < 16; j++) acc[j] = 0.f;
    const float* w = Wdec + (size_t)a * D_;
    for (int k = 0; k < D_; k += 4) {
        const float4 wv = *(const float4*)(w + k);
        #pragma unroll
        for (int j = 0; j < 16; j++) {
            acc[j] = fmaf(wv.x, dhs[j][k + 0],
                     fmaf(wv.y, dhs[j][k + 1],
                     fmaf(wv.z, dhs[j][k + 2],
                     fmaf(wv.w, dhs[j][k + 3], acc[j]))));
        }
    }
    #pragma unroll
    for (int j = 0; j < 16; j++)
        g_att2[(size_t)(b0 + j) * A_ + a] = acc[j] + bias;
}

// ---------------------------------------------------------------------------
// Kernel 2: split-bf16 HMMA GEMM + fused epilogue.
//  Tile 128m x 128a, BK=32, 2 stages, 2 CTAs/SM, warp tile 64x32.
//  Term-major MMA issue: all hh, then all hl, then all lh (16-acc reuse dist).
// ---------------------------------------------------------------------------
#define BM 128
#define BK 32
#define NCHUNK (E_ / BK)     // 64
#define ROWB 80              // padded row bytes (32 bf16 = 64B -> 80B)

#define SM_ATT2   0          // 4*128*4 = 2048
#define SM_WF     2048       // 128*4 = 512
#define SM_RED    2560       // 128*4*4 = 2048
#define SM_STAGE0 5120
#define AH_OFF    0
#define AL_OFF    10240
#define BH_OFF    20480
#define BL_OFF    30720
#define STG       40960
#define SMEM_TOTAL (SM_STAGE0 + 2 * STG)   // 87040

__global__ __launch_bounds__(256, 2)
void k_main(const float* __restrict__ enc, const float* __restrict__ Wfull)
{
    extern __shared__ char smem[];
    const int t = threadIdx.x;
    const int lane = t & 31, wid = t >> 5;
    const int warp_m = wid & 1, warp_n = wid >> 1;
    const int chunkA = blockIdx.x;         // 0..3
    const int m0 = blockIdx.y * BM;
    const int a0 = chunkA * 128;
    const uint32_t sbase = smem_u32(smem);

    // epilogue constants
    const int b_first = m0 / N_;
    {
        float* att2s = (float*)(smem + SM_ATT2);
        for (int i = t; i < 4 * 128; i += 256) {
            const int br = b_first + (i >> 7);
            att2s[i] = (br < B_) ? g_att2[(size_t)br * A_ + a0 + (i & 127)] : 0.f;
        }
        if (t < 128) ((float*)(smem + SM_WF))[t] = Wfull[a0 + t];
    }

    // ---- loaders ----
    float4 areg[4];
    const float* ap = enc + (size_t)(m0 + (t >> 1)) * E_ + (t & 1) * 16;

    auto ldA = [&](int c) {
        const float4* p = (const float4*)(ap + c * BK);
        #pragma unroll
        for (int i = 0; i < 4; i++) areg[i] = p[i];
    };
    auto stsA = [&](int j) {
        char* bh = smem + SM_STAGE0 + j * STG + AH_OFF;
        char* bl = smem + SM_STAGE0 + j * STG + AL_OFF;
        const uint32_t off = (uint32_t)((t >> 1) * ROWB + (t & 1) * 32);
        uint32_t h[8], l[8];
        #pragma unroll
        for (int i = 0; i < 4; i++) {
            const float4 x = areg[i];
            __nv_bfloat162 hh0 = __floats2bfloat162_rn(x.x, x.y);
            __nv_bfloat162 hh1 = __floats2bfloat162_rn(x.z, x.w);
            __nv_bfloat162 ll0 = __floats2bfloat162_rn(x.x - __low2float(hh0), x.y - __high2float(hh0));
            __nv_bfloat162 ll1 = __floats2bfloat162_rn(x.z - __low2float(hh1), x.w - __high2float(hh1));
            h[2 * i] = *(uint32_t*)&hh0; h[2 * i + 1] = *(uint32_t*)&hh1;
            l[2 * i] = *(uint32_t*)&ll0; l[2 * i + 1] = *(uint32_t*)&ll1;
        }
        *(uint4*)(bh + off)      = make_uint4(h[0], h[1], h[2], h[3]);
        *(uint4*)(bh + off + 16) = make_uint4(h[4], h[5], h[6], h[7]);
        *(uint4*)(bl + off)      = make_uint4(l[0], l[1], l[2], l[3]);
        *(uint4*)(bl + off + 16) = make_uint4(l[4], l[5], l[6], l[7]);
    };
    auto cpB = [&](int c, int j) {
        const uint32_t bh = sbase + SM_STAGE0 + j * STG + BH_OFF;
        const uint32_t bl = sbase + SM_STAGE0 + j * STG + BL_OFF;
        #pragma unroll
        for (int i = 0; i < 2; i++) {
            const int idx = t + 256 * i;
            const int row = idx >> 2, u = idx & 3;
            const uint32_t d = (uint32_t)(row * ROWB + u * 16);
            const size_t gs = (size_t)(a0 + row) * E_ + c * BK + u * 8;
            cpasync16(bh + d, g_Wh + gs);
            cpasync16(bl + d, g_Wl + gs);
        }
        asm volatile("cp.async.commit_group;" ::: "memory");
    };

    float acc[4][4][4];
    #pragma unroll
    for (int i = 0; i < 4; i++)
        #pragma unroll
        for (int j = 0; j < 4; j++)
            #pragma unroll
            for (int q = 0; q < 4; q++) acc[i][j][q] = 0.f;

    // ---- prologue ----
    ldA(0);
    __syncthreads();
    stsA(0);
    cpB(0, 0);
    ldA(1);

    // ---- pipeline ----
    for (int c = 0; c < NCHUNK; c++) {
        const int j = c & 1, jn = j ^ 1;

        asm volatile("cp.async.wait_group 0;" ::: "memory");
        __syncthreads();

        if (c + 1 < NCHUNK) {
            stsA(jn);
            cpB(c + 1, jn);
            if (c + 2 < NCHUNK) ldA(c + 2);
        }

        const uint32_t abase = sbase + SM_STAGE0 + j * STG;
        #pragma unroll
        for (int ks = 0; ks < 2; ks++) {
            uint32_t ah[4][4], al[4][4], bhf[4][2], blf[4][2];
            #pragma unroll
            for (int mt = 0; mt < 4; mt++) {
                const uint32_t addr = abase
                    + (uint32_t)((warp_m * 64 + mt * 16 + (lane & 15)) * ROWB)
                    + (uint32_t)((lane >> 4) * 16 + ks * 32);
                ldsm4(ah[mt], addr + AH_OFF);
                ldsm4(al[mt], addr + AL_OFF);
            }
            #pragma unroll
            for (int pt = 0; pt < 2; pt++) {
                const uint32_t row = (uint32_t)(warp_n * 32 + pt * 16
                                   + ((lane >> 4) << 3) + (lane & 7));
                const uint32_t addr = abase + (uint32_t)(row * ROWB)
                    + (uint32_t)(((lane >> 3) & 1) * 16 + ks * 32);
                uint32_t r[4];
                ldsm4(r, addr + BH_OFF);
                bhf[2 * pt][0] = r[0]; bhf[2 * pt][1] = r[1];
                bhf[2 * pt + 1][0] = r[2]; bhf[2 * pt + 1][1] = r[3];
                ldsm4(r, addr + BL_OFF);
                blf[2 * pt][0] = r[0]; blf[2 * pt][1] = r[1];
                blf[2 * pt + 1][0] = r[2]; blf[2 * pt + 1][1] = r[3];
            }
            // term-major issue: 16 independent accumulators per term.
            #pragma unroll
            for (int mt = 0; mt < 4; mt++)
                #pragma unroll
                for (int nt = 0; nt < 4; nt++)
                    mma16816(acc[mt][nt], ah[mt], bhf[nt]);
            #pragma unroll
            for (int mt = 0; mt < 4; mt++)
                #pragma unroll
                for (int nt = 0; nt < 4; nt++)
                    mma16816(acc[mt][nt], ah[mt], blf[nt]);
            #pragma unroll
            for (int mt = 0; mt < 4; mt++)
                #pragma unroll
                for (int nt = 0; nt < 4; nt++)
                    mma16816(acc[mt][nt], al[mt], bhf[nt]);
        }
    }

    // ---- epilogue ----
    const float* att2s = (const float*)(smem + SM_ATT2);
    const float* wfs   = (const float*)(smem + SM_WF);
    float* red         = (float*)(smem + SM_RED);   // [128][4]

    #pragma unroll
    for (int mt = 0; mt < 4; mt++) {
        const int r0 = warp_m * 64 + mt * 16 + (lane >> 2);
        const int r1 = r0 + 8;
        const int bl0 = (m0 + r0) / N_ - b_first;
        const int bl1 = (m0 + r1) / N_ - b_first;
        float s0 = 0.f, s1 = 0.f;
        #pragma unroll
        for (int nt = 0; nt < 4; nt++) {
            const int cb = warp_n * 32 + nt * 8 + (lane & 3) * 2;
            float v;
            v = fmaxf(acc[mt][nt][0] + att2s[bl0 * 128 + cb],     0.f); s0 = fmaf(v, wfs[cb],     s0);
            v = fmaxf(acc[mt][nt][1] + att2s[bl0 * 128 + cb + 1], 0.f); s0 = fmaf(v, wfs[cb + 1], s0);
            v = fmaxf(acc[mt][nt][2] + att2s[bl1 * 128 + cb],     0.f); s1 = fmaf(v, wfs[cb],     s1);
            v = fmaxf(acc[mt][nt][3] + att2s[bl1 * 128 + cb + 1], 0.f); s1 = fmaf(v, wfs[cb + 1], s1);
        }
        s0 += __shfl_xor_sync(0xffffffffu, s0, 1);
        s0 += __shfl_xor_sync(0xffffffffu, s0, 2);
        s1 += __shfl_xor_sync(0xffffffffu, s1, 1);
        s1 += __shfl_xor_sync(0xffffffffu, s1, 2);
        if ((lane & 3) == 0) {
            red[r0 * 4 + warp_n] = s0;
            red[r1 * 4 + warp_n] = s1;
        }
    }
    __syncthreads();
    if (t < 128) {
        const float s = red[t * 4] + red[t * 4 + 1] + red[t * 4 + 2] + red[t * 4 + 3];
        g_attp[(size_t)chunkA * M_ + m0 + t] = s;
    }
}

// ---------------------------------------------------------------------------
// Kernel 3: beta, softmax*beta, awe, final writes.
// ---------------------------------------------------------------------------
__global__ __launch_bounds__(256)
void k_final(const float* __restrict__ enc, const float* __restrict__ dh,
             const float* __restrict__ Wsig, const float* __restrict__ bsig,
             const float* __restrict__ bfull, float* __restrict__ out)
{
    const int b = blockIdx.x;
    const int t = threadIdx.x;
    __shared__ float dhs[D_];
    __shared__ float red[256];
    __shared__ float alph[N_];
    __shared__ float beta_s;

    for (int i = t; i < D_; i += 256) dhs[i] = dh[(size_t)b * D_ + i];
    __syncthreads();

    red[t] = dhs[t] * Wsig[t] + dhs[t + 256] * Wsig[t + 256];
    __syncthreads();
    for (int s = 128; s > 0; s >>= 1) {
        if (t < s) red[t] += red[t + s];
        __syncthreads();
    }
    if (t == 0) beta_s = 1.f / (1.f + expf(-(red[0] + bsig[0])));

    if (t < N_) {
        float v = bfull[0];
        #pragma unroll
        for (int c = 0; c < 4; c++) v += g_attp[(size_t)c * M_ + b * N_ + t];
        alph[t] = v;
    }
    __syncthreads();

    if (t == 0) {
        float mx = -1e30f;
        for (int n = 0; n < N_; n++) mx = fmaxf(mx, alph[n]);
        float sm = 0.f;
        for (int n = 0; n < N_; n++) { float e = expf(alph[n] - mx); alph[n] = e; sm += e; }
        const float scale = beta_s / sm;
        for (int n = 0; n < N_; n++) alph[n] *= scale;
    }
    __syncthreads();

    if (t < N_) out[ALPHA_OFF + b * N_ + t] = alph[t];
    if (t == 0) out[BETA_OFF + b] = beta_s;

    const float* eb = enc + (size_t)b * N_ * E_;
    for (int ebase = 0; ebase < E_; ebase += 1024) {
        float a0 = 0.f, a1 = 0.f, a2v = 0.f, a3 = 0.f;
        #pragma unroll 7
        for (int n = 0; n < N_; n++) {
            const float* p = eb + (size_t)n * E_ + ebase + t;
            const float al = alph[n];
            a0  = fmaf(al, p[0],   a0);
            a1  = fmaf(al, p[256], a1);
            a2v = fmaf(al, p[512], a2v);
            a3  = fmaf(al, p[768], a3);
        }
        float* o = out + AWE_OFF + (size_t)b * E_ + ebase + t;
        o[0]   = a0;
        o[256] = a1;
        o[512] = a2v;
        o[768] = a3;
    }
}

// ---------------------------------------------------------------------------
extern "C" void kernel_launch(void* const* d_in, const int* in_sizes, int n_in,
                              void* d_out, int out_size)
{
    (void)in_sizes; (void)n_in; (void)out_size;
    const float* enc  = (const float*)d_in[0];
    const float* dh   = (const float*)d_in[1];
    const float* Wenc = (const float*)d_in[2];
    const float* benc = (const float*)d_in[3];
    const float* Wdec = (const float*)d_in[4];
    const float* bdec = (const float*)d_in[5];
    const float* Wsig = (const float*)d_in[6];
    const float* bsig = (const float*)d_in[7];
    const float* Wful = (const float*)d_in[8];
    const float* bful = (const float*)d_in[9];
    float* out = (float*)d_out;

    cudaFuncSetAttribute(k_main, cudaFuncAttributeMaxDynamicSharedMemorySize, SMEM_TOTAL);

    k_wconv<<<(A_ * E_) / 1024, 256>>>(Wenc);
    k_att2<<<dim3(B_ / 16, 2), 256>>>(dh, Wdec, benc, bdec);
    k_main<<<dim3(4, M_ / BM), 256, SMEM_TOTAL>>>(enc, Wful);
    k_final<<<B_, 256>>>(enc, dh, Wsig, bsig, bful, out);
}

// round 8
// speedup vs baseline: 3.0593x; 1.4161x over previous
#include <cuda_runtime.h>
#include <cuda_bf16.h>
#include <cuda_fp16.h>
#include <math.h>
#include <stdint.h>

#define B_ 1024
#define N_ 49
#define E_ 2048
#define D_ 512
#define A_ 512
#define M_ (B_ * N_)   // 50176

// out layout: [awe B*E][alpha B*N][beta B]
#define AWE_OFF   0
#define ALPHA_OFF (B_ * E_)
#define BETA_OFF  (ALPHA_OFF + B_ * N_)

// scratch (device globals)
__device__ float g_att2[B_ * A_];                 // [B, A] = att2 + b_dec + b_enc
__device__ float g_attp[4 * M_];                  // 4 a-chunk partials of att[m]
__device__ __half g_Wf[A_ * E_];                  // W_enc fp16

// ---------------------------------------------------------------------------
__device__ __forceinline__ uint32_t smem_u32(const void* p) {
    return (uint32_t)__cvta_generic_to_shared((void*)p);
}
__device__ __forceinline__ void cpasync16(uint32_t dst, const void* src) {
    asm volatile("cp.async.cg.shared.global [%0], [%1], 16;" :: "r"(dst), "l"(src));
}
__device__ __forceinline__ void ldsm4(uint32_t* r, uint32_t addr) {
    asm volatile("ldmatrix.sync.aligned.m8n8.x4.shared.b16 {%0,%1,%2,%3}, [%4];"
                 : "=r"(r[0]), "=r"(r[1]), "=r"(r[2]), "=r"(r[3]) : "r"(addr));
}
// fp16 inputs, fp32 accumulate; non-volatile so ptxas can schedule.
__device__ __forceinline__ void mma16816(float* c, const uint32_t* a, const uint32_t* b) {
    asm("mma.sync.aligned.m16n8k16.row.col.f32.f16.f16.f32 "
        "{%0,%1,%2,%3}, {%4,%5,%6,%7}, {%8,%9}, {%0,%1,%2,%3};"
        : "+f"(c[0]), "+f"(c[1]), "+f"(c[2]), "+f"(c[3])
        : "r"(a[0]), "r"(a[1]), "r"(a[2]), "r"(a[3]), "r"(b[0]), "r"(b[1]));
}

// ---------------------------------------------------------------------------
// Kernel 0: convert W_enc to fp16
// ---------------------------------------------------------------------------
__global__ __launch_bounds__(256)
void k_wconv(const float* __restrict__ W)
{
    const int i = (blockIdx.x * 256 + threadIdx.x) * 4;
    const float4 x = *(const float4*)(W + i);
    ((__half2*)g_Wf)[i / 2]     = __floats2half2_rn(x.x, x.y);
    ((__half2*)g_Wf)[i / 2 + 1] = __floats2half2_rn(x.z, x.w);
}

// ---------------------------------------------------------------------------
// Kernel 1: att2[b,a] = dot(dh[b], W_dec[a]) + b_dec[a] + b_enc[a]
// ---------------------------------------------------------------------------
__global__ __launch_bounds__(256)
void k_att2(const float* __restrict__ dh, const float* __restrict__ Wdec,
            const float* __restrict__ b_enc, const float* __restrict__ b_dec)
{
    __shared__ float dhs[16][D_];
    const int b0 = blockIdx.x * 16;
    const int t = threadIdx.x;
    for (int i = t; i < 16 * D_; i += 256)
        dhs[i >> 9][i & 511] = dh[(size_t)b0 * D_ + i];
    __syncthreads();

    const int a = blockIdx.y * 256 + t;
    const float bias = b_dec[a] + b_enc[a];
    float acc[16];
    #pragma unroll
    for (int j = 0; j < 16; j++) acc[j] = 0.f;
    const float* w = Wdec + (size_t)a * D_;
    for (int k = 0; k < D_; k += 4) {
        const float4 wv = *(const float4*)(w + k);
        #pragma unroll
        for (int j = 0; j < 16; j++) {
            acc[j] = fmaf(wv.x, dhs[j][k + 0],
                     fmaf(wv.y, dhs[j][k + 1],
                     fmaf(wv.z, dhs[j][k + 2],
                     fmaf(wv.w, dhs[j][k + 3], acc[j]))));
        }
    }
    #pragma unroll
    for (int j = 0; j < 16; j++)
        g_att2[(size_t)(b0 + j) * A_ + a] = acc[j] + bias;
}

// ---------------------------------------------------------------------------
// Kernel 2: 2-term fp16 HMMA GEMM + fused epilogue.
//  A = enc split hi/lo fp16 (in-kernel), B = W_enc single fp16.
//  D += Ah*B + Al*B (fp32 accum). Tile 128x128, BK=32, 3 stages, 2 CTAs/SM.
// ---------------------------------------------------------------------------
#define BM 128
#define BK 32
#define NCHUNK (E_ / BK)     // 64
#define ROWB 80              // padded row bytes (32 fp16 = 64B -> 80B)

#define SM_ATT2   0          // 4*128*4 = 2048
#define SM_WF     2048       // 128*4 = 512
#define SM_RED    2560       // 128*4*4 = 2048
#define SM_STAGE0 5120
#define AH_OFF    0          // 128*80 = 10240
#define AL_OFF    10240
#define BF_OFF    20480      // 128*80 = 10240
#define STG       30720
#define NSTAGE    3
#define SMEM_TOTAL (SM_STAGE0 + NSTAGE * STG)   // 97280

__global__ __launch_bounds__(256, 2)
void k_main(const float* __restrict__ enc, const float* __restrict__ Wfull)
{
    extern __shared__ char smem[];
    const int t = threadIdx.x;
    const int lane = t & 31, wid = t >> 5;
    const int warp_m = wid & 1, warp_n = wid >> 1;
    const int chunkA = blockIdx.x;         // 0..3
    const int m0 = blockIdx.y * BM;
    const int a0 = chunkA * 128;
    const uint32_t sbase = smem_u32(smem);

    // epilogue constants
    const int b_first = m0 / N_;
    {
        float* att2s = (float*)(smem + SM_ATT2);
        for (int i = t; i < 4 * 128; i += 256) {
            const int br = b_first + (i >> 7);
            att2s[i] = (br < B_) ? g_att2[(size_t)br * A_ + a0 + (i & 127)] : 0.f;
        }
        if (t < 128) ((float*)(smem + SM_WF))[t] = Wfull[a0 + t];
    }

    // ---- loaders ----
    float4 areg[4];
    const float* ap = enc + (size_t)(m0 + (t >> 1)) * E_ + (t & 1) * 16;

    auto ldA = [&](int c) {
        const float4* p = (const float4*)(ap + c * BK);
        #pragma unroll
        for (int i = 0; i < 4; i++) areg[i] = p[i];
    };
    auto stsA = [&](int st) {
        char* bh = smem + SM_STAGE0 + st * STG + AH_OFF;
        char* bl = smem + SM_STAGE0 + st * STG + AL_OFF;
        const uint32_t off = (uint32_t)((t >> 1) * ROWB + (t & 1) * 32);
        uint32_t h[8], l[8];
        #pragma unroll
        for (int i = 0; i < 4; i++) {
            const float4 x = areg[i];
            __half2 hh0 = __floats2half2_rn(x.x, x.y);
            __half2 hh1 = __floats2half2_rn(x.z, x.w);
            __half2 ll0 = __floats2half2_rn(x.x - __low2float(hh0), x.y - __high2float(hh0));
            __half2 ll1 = __floats2half2_rn(x.z - __low2float(hh1), x.w - __high2float(hh1));
            h[2 * i] = *(uint32_t*)&hh0; h[2 * i + 1] = *(uint32_t*)&hh1;
            l[2 * i] = *(uint32_t*)&ll0; l[2 * i + 1] = *(uint32_t*)&ll1;
        }
        *(uint4*)(bh + off)      = make_uint4(h[0], h[1], h[2], h[3]);
        *(uint4*)(bh + off + 16) = make_uint4(h[4], h[5], h[6], h[7]);
        *(uint4*)(bl + off)      = make_uint4(l[0], l[1], l[2], l[3]);
        *(uint4*)(bl + off + 16) = make_uint4(l[4], l[5], l[6], l[7]);
    };
    auto cpB = [&](int c, int st) {
        const uint32_t bf = sbase + SM_STAGE0 + st * STG + BF_OFF;
        #pragma unroll
        for (int i = 0; i < 2; i++) {
            const int idx = t + 256 * i;
            const int row = idx >> 2, u = idx & 3;
            const uint32_t d = (uint32_t)(row * ROWB + u * 16);
            cpasync16(bf + d, g_Wf + (size_t)(a0 + row) * E_ + c * BK + u * 8);
        }
        asm volatile("cp.async.commit_group;" ::: "memory");
    };

    float acc[4][4][4];
    #pragma unroll
    for (int i = 0; i < 4; i++)
        #pragma unroll
        for (int j = 0; j < 4; j++)
            #pragma unroll
            for (int q = 0; q < 4; q++) acc[i][j][q] = 0.f;

    // ---- prologue: fill stages 0,1 ----
    ldA(0);
    __syncthreads();
    stsA(0); cpB(0, 0);
    ldA(1);
    stsA(1); cpB(1, 1);
    ldA(2);

    int st_c = 0;
    // ---- pipeline ----
    for (int c = 0; c < NCHUNK; c++) {
        asm volatile("cp.async.wait_group 1;" ::: "memory");
        __syncthreads();   // B(chunk c) visible; stage (st_c+2)%3 free

        if (c + 2 < NCHUNK) {
            const int st_f = (st_c + 2 >= NSTAGE) ? st_c + 2 - NSTAGE : st_c + 2;
            stsA(st_f);                     // areg holds chunk c+2
            cpB(c + 2, st_f);
            if (c + 3 < NCHUNK) ldA(c + 3);
        } else {
            asm volatile("cp.async.commit_group;" ::: "memory");
        }

        const uint32_t abase = sbase + SM_STAGE0 + st_c * STG;
        #pragma unroll
        for (int ks = 0; ks < 2; ks++) {
            uint32_t ah[4][4], al[4][4], bf[4][2];
            #pragma unroll
            for (int mt = 0; mt < 4; mt++) {
                const uint32_t addr = abase
                    + (uint32_t)((warp_m * 64 + mt * 16 + (lane & 15)) * ROWB)
                    + (uint32_t)((lane >> 4) * 16 + ks * 32);
                ldsm4(ah[mt], addr + AH_OFF);
                ldsm4(al[mt], addr + AL_OFF);
            }
            #pragma unroll
            for (int pt = 0; pt < 2; pt++) {
                const uint32_t row = (uint32_t)(warp_n * 32 + pt * 16
                                   + ((lane >> 4) << 3) + (lane & 7));
                const uint32_t addr = abase + BF_OFF + (uint32_t)(row * ROWB)
                    + (uint32_t)(((lane >> 3) & 1) * 16 + ks * 32);
                uint32_t r[4];
                ldsm4(r, addr);
                bf[2 * pt][0] = r[0]; bf[2 * pt][1] = r[1];
                bf[2 * pt + 1][0] = r[2]; bf[2 * pt + 1][1] = r[3];
            }
            // term-major: 16 independent accs per term
            #pragma unroll
            for (int mt = 0; mt < 4; mt++)
                #pragma unroll
                for (int nt = 0; nt < 4; nt++)
                    mma16816(acc[mt][nt], ah[mt], bf[nt]);
            #pragma unroll
            for (int mt = 0; mt < 4; mt++)
                #pragma unroll
                for (int nt = 0; nt < 4; nt++)
                    mma16816(acc[mt][nt], al[mt], bf[nt]);
        }
        st_c = (st_c + 1 >= NSTAGE) ? 0 : st_c + 1;
    }

    // ---- epilogue ----
    const float* att2s = (const float*)(smem + SM_ATT2);
    const float* wfs   = (const float*)(smem + SM_WF);
    float* red         = (float*)(smem + SM_RED);   // [128][4]

    #pragma unroll
    for (int mt = 0; mt < 4; mt++) {
        const int r0 = warp_m * 64 + mt * 16 + (lane >> 2);
        const int r1 = r0 + 8;
        const int bl0 = (m0 + r0) / N_ - b_first;
        const int bl1 = (m0 + r1) / N_ - b_first;
        float s0 = 0.f, s1 = 0.f;
        #pragma unroll
        for (int nt = 0; nt < 4; nt++) {
            const int cb = warp_n * 32 + nt * 8 + (lane & 3) * 2;
            float v;
            v = fmaxf(acc[mt][nt][0] + att2s[bl0 * 128 + cb],     0.f); s0 = fmaf(v, wfs[cb],     s0);
            v = fmaxf(acc[mt][nt][1] + att2s[bl0 * 128 + cb + 1], 0.f); s0 = fmaf(v, wfs[cb + 1], s0);
            v = fmaxf(acc[mt][nt][2] + att2s[bl1 * 128 + cb],     0.f); s1 = fmaf(v, wfs[cb],     s1);
            v = fmaxf(acc[mt][nt][3] + att2s[bl1 * 128 + cb + 1], 0.f); s1 = fmaf(v, wfs[cb + 1], s1);
        }
        s0 += __shfl_xor_sync(0xffffffffu, s0, 1);
        s0 += __shfl_xor_sync(0xffffffffu, s0, 2);
        s1 += __shfl_xor_sync(0xffffffffu, s1, 1);
        s1 += __shfl_xor_sync(0xffffffffu, s1, 2);
        if ((lane & 3) == 0) {
            red[r0 * 4 + warp_n] = s0;
            red[r1 * 4 + warp_n] = s1;
        }
    }
    __syncthreads();
    if (t < 128) {
        const float s = red[t * 4] + red[t * 4 + 1] + red[t * 4 + 2] + red[t * 4 + 3];
        g_attp[(size_t)chunkA * M_ + m0 + t] = s;
    }
}

// ---------------------------------------------------------------------------
// Kernel 3: beta, softmax*beta, awe (float4 loads), final writes.
// ---------------------------------------------------------------------------
__global__ __launch_bounds__(256)
void k_final(const float* __restrict__ enc, const float* __restrict__ dh,
             const float* __restrict__ Wsig, const float* __restrict__ bsig,
             const float* __restrict__ bfull, float* __restrict__ out)
{
    const int b = blockIdx.x;
    const int t = threadIdx.x;
    __shared__ float dhs[D_];
    __shared__ float red[256];
    __shared__ float alph[N_];
    __shared__ float beta_s;

    for (int i = t; i < D_; i += 256) dhs[i] = dh[(size_t)b * D_ + i];
    __syncthreads();

    red[t] = dhs[t] * Wsig[t] + dhs[t + 256] * Wsig[t + 256];
    __syncthreads();
    for (int s = 128; s > 0; s >>= 1) {
        if (t < s) red[t] += red[t + s];
        __syncthreads();
    }
    if (t == 0) beta_s = 1.f / (1.f + expf(-(red[0] + bsig[0])));

    if (t < N_) {
        float v = bfull[0];
        #pragma unroll
        for (int c = 0; c < 4; c++) v += g_attp[(size_t)c * M_ + b * N_ + t];
        alph[t] = v;
    }
    __syncthreads();

    if (t == 0) {
        float mx = -1e30f;
        for (int n = 0; n < N_; n++) mx = fmaxf(mx, alph[n]);
        float sm = 0.f;
        for (int n = 0; n < N_; n++) { float e = expf(alph[n] - mx); alph[n] = e; sm += e; }
        const float scale = beta_s / sm;
        for (int n = 0; n < N_; n++) alph[n] *= scale;
    }
    __syncthreads();

    if (t < N_) out[ALPHA_OFF + b * N_ + t] = alph[t];
    if (t == 0) out[BETA_OFF + b] = beta_s;

    // awe: float4 loads, 2 accumulators (E/4 = 512 float4, 256 threads)
    const float4* eb4 = (const float4*)(enc + (size_t)b * N_ * E_);
    float4 s0 = make_float4(0.f, 0.f, 0.f, 0.f);
    float4 s1 = make_float4(0.f, 0.f, 0.f, 0.f);
    #pragma unroll 7
    for (int n = 0; n < N_; n++) {
        const float al = alph[n];
        const float4 v0 = eb4[n * 512 + t];
        const float4 v1 = eb4[n * 512 + t + 256];
        s0.x = fmaf(al, v0.x, s0.x); s0.y = fmaf(al, v0.y, s0.y);
        s0.z = fmaf(al, v0.z, s0.z); s0.w = fmaf(al, v0.w, s0.w);
        s1.x = fmaf(al, v1.x, s1.x); s1.y = fmaf(al, v1.y, s1.y);
        s1.z = fmaf(al, v1.z, s1.z); s1.w = fmaf(al, v1.w, s1.w);
    }
    float4* o4 = (float4*)(out + AWE_OFF + (size_t)b * E_);
    o4[t] = s0;
    o4[t + 256] = s1;
}

// ---------------------------------------------------------------------------
extern "C" void kernel_launch(void* const* d_in, const int* in_sizes, int n_in,
                              void* d_out, int out_size)
{
    (void)in_sizes; (void)n_in; (void)out_size;
    const float* enc  = (const float*)d_in[0];
    const float* dh   = (const float*)d_in[1];
    const float* Wenc = (const float*)d_in[2];
    const float* benc = (const float*)d_in[3];
    const float* Wdec = (const float*)d_in[4];
    const float* bdec = (const float*)d_in[5];
    const float* Wsig = (const float*)d_in[6];
    const float* bsig = (const float*)d_in[7];
    const float* Wful = (const float*)d_in[8];
    const float* bful = (const float*)d_in[9];
    float* out = (float*)d_out;

    cudaFuncSetAttribute(k_main, cudaFuncAttributeMaxDynamicSharedMemorySize, SMEM_TOTAL);

    k_wconv<<<(A_ * E_) / 1024, 256>>>(Wenc);
    k_att2<<<dim3(B_ / 16, 2), 256>>>(dh, Wdec, benc, bdec);
    k_main<<<dim3(4, M_ / BM), 256, SMEM_TOTAL>>>(enc, Wful);
    k_final<<<B_, 256>>>(enc, dh, Wsig, bsig, bful, out);
}